// round 14
// baseline (speedup 1.0000x reference)
#include <cuda_runtime.h>
#include <float.h>

// Fused sRGB->CIELab + per-image L min-max normalization. Two-kernel.
// R14: hybrid f32x2 packing — scalar math around MUFU ops (no pack/unpack
// movs there), packed fma.rn.f32x2 ONLY for mov-free chains: the 3x3 matrix
// and the final L/a/b computation.
// K1: per-image Y min/max (L monotonic in Y), 4 CTAs/image.
// K2: full Lab + normalize, 8 CTAs/image, reverse image order (L2 reuse),
//     streaming float4 stores.

#define NPIX      16384
#define NIMG      512
#define K1_SUBS   4
#define K2_SUBS   8
#define THREADS   256
#define K1_PX     (NPIX / K1_SUBS)         // 4096
#define K2_PX     (NPIX / K2_SUBS)         // 2048
#define K1_GROUPS (K1_PX / (THREADS * 4))  // 4
#define K2_GROUPS (K2_PX / (THREADS * 4))  // 2

typedef unsigned long long u64;

__device__ float g_pmin[NIMG * K1_SUBS];
__device__ float g_pmax[NIMG * K1_SUBS];

// ---------------- f32x2 packed helpers ----------------
__device__ __forceinline__ u64 pk2(float lo, float hi) {
    u64 d; asm("mov.b64 %0, {%1, %2};" : "=l"(d) : "f"(lo), "f"(hi)); return d;
}
__device__ __forceinline__ void upk2(u64 d, float& lo, float& hi) {
    asm("mov.b64 {%0, %1}, %2;" : "=f"(lo), "=f"(hi) : "l"(d));
}
__device__ __forceinline__ u64 fma2(u64 a, u64 b, u64 c) {
    u64 d; asm("fma.rn.f32x2 %0, %1, %2, %3;" : "=l"(d) : "l"(a), "l"(b), "l"(c)); return d;
}
__device__ __forceinline__ u64 mul2(u64 a, u64 b) {
    u64 d; asm("mul.rn.f32x2 %0, %1, %2;" : "=l"(d) : "l"(a), "l"(b)); return d;
}

__device__ __forceinline__ float mufu_lg2(float x) {
    float r; asm("lg2.approx.f32 %0, %1;" : "=f"(r) : "f"(x)); return r;
}
__device__ __forceinline__ float mufu_ex2(float x) {
    float r; asm("ex2.approx.f32 %0, %1;" : "=f"(r) : "f"(x)); return r;
}
__device__ __forceinline__ float mufu_rcp(float x) {
    float r; asm("rcp.approx.f32 %0, %1;" : "=f"(r) : "f"(x)); return r;
}

// scalar gamma (4 slots + 2 MUFU, no packing overhead)
__device__ __forceinline__ float srgb_lin(float c) {
    float t = fmaf(c, 1.0f / 1.055f, 0.055f / 1.055f);
    float p = mufu_ex2(2.4f * mufu_lg2(t));
    return (c > 0.04045f) ? p : c * (1.0f / 12.92f);
}

// scalar Lab f() (3 slots + 2 MUFU)
__device__ __forceinline__ float xyz_f(float t) {
    float cr = mufu_ex2((1.0f / 3.0f) * mufu_lg2(t));
    return (t > 0.008856f) ? cr : fmaf(t, 7.787f, 16.0f / 116.0f);
}

// ---------------------------------------------------------------- K1
__global__ void __launch_bounds__(THREADS)
minmax_kernel(const float* __restrict__ x) {
    __shared__ float red[16];
    const int bid = blockIdx.x;
    const int tid = threadIdx.x;

    const float4* in4 = (const float4*)x + bid * (K1_PX * 3 / 4);

    const u64 MY0 = pk2(0.212671f, 0.212671f);
    const u64 MY1 = pk2(0.715160f, 0.715160f);
    const u64 MY2 = pk2(0.072169f, 0.072169f);

    float ymin = FLT_MAX, ymax = -FLT_MAX;

    #pragma unroll
    for (int j = 0; j < K1_GROUPS; j++) {
        int gi = tid + j * THREADS;
        float4 v0 = in4[gi * 3 + 0];
        float4 v1 = in4[gi * 3 + 1];
        float4 v2 = in4[gi * 3 + 2];

        // scalar gamma, then pack pairs for the Y dot-product
        u64 rA = pk2(srgb_lin(v0.x), srgb_lin(v0.w));
        u64 gA = pk2(srgb_lin(v0.y), srgb_lin(v1.x));
        u64 bA = pk2(srgb_lin(v0.z), srgb_lin(v1.y));
        u64 rB = pk2(srgb_lin(v1.z), srgb_lin(v2.y));
        u64 gB = pk2(srgb_lin(v1.w), srgb_lin(v2.z));
        u64 bB = pk2(srgb_lin(v2.x), srgb_lin(v2.w));

        u64 yA = fma2(rA, MY0, fma2(gA, MY1, mul2(bA, MY2)));
        u64 yB = fma2(rB, MY0, fma2(gB, MY1, mul2(bB, MY2)));

        float y0, y1, y2, y3;
        upk2(yA, y0, y1);  upk2(yB, y2, y3);
        ymin = fminf(fminf(fminf(ymin, y0), fminf(y1, y2)), y3);
        ymax = fmaxf(fmaxf(fmaxf(ymax, y0), fmaxf(y1, y2)), y3);
    }

    #pragma unroll
    for (int off = 16; off > 0; off >>= 1) {
        ymin = fminf(ymin, __shfl_xor_sync(0xffffffffu, ymin, off));
        ymax = fmaxf(ymax, __shfl_xor_sync(0xffffffffu, ymax, off));
    }
    int lane = tid & 31, wid = tid >> 5;
    if (lane == 0) { red[wid] = ymin; red[8 + wid] = ymax; }
    __syncthreads();
    if (tid == 0) {
        float mn = red[0], mx = red[8];
        #pragma unroll
        for (int i = 1; i < 8; i++) {
            mn = fminf(mn, red[i]);
            mx = fmaxf(mx, red[8 + i]);
        }
        g_pmin[bid] = mn;
        g_pmax[bid] = mx;
    }
}

// ---------------------------------------------------------------- K2
__global__ void __launch_bounds__(THREADS)
convert_kernel(const float* __restrict__ x, float* __restrict__ out) {
    const int bid = blockIdx.x;
    const int img = (NIMG - 1) - (bid >> 3);   // reverse order for L2 reuse
    const int sub = bid & 7;
    const int tid = threadIdx.x;

    float ymn = fminf(fminf(g_pmin[img * 4 + 0], g_pmin[img * 4 + 1]),
                      fminf(g_pmin[img * 4 + 2], g_pmin[img * 4 + 3]));
    float ymx = fmaxf(fmaxf(g_pmax[img * 4 + 0], g_pmax[img * 4 + 1]),
                      fmaxf(g_pmax[img * 4 + 2], g_pmax[img * 4 + 3]));
    float fmin = xyz_f(ymn);
    float sf   = mufu_rcp(xyz_f(ymx) - fmin);
    const u64 SF2  = pk2(sf, sf);
    const u64 NSF2 = pk2(-fmin * sf, -fmin * sf);

    const u64 M00 = pk2(0.412453f / 0.95047f, 0.412453f / 0.95047f);
    const u64 M01 = pk2(0.357580f / 0.95047f, 0.357580f / 0.95047f);
    const u64 M02 = pk2(0.180423f / 0.95047f, 0.180423f / 0.95047f);
    const u64 M10 = pk2(0.212671f, 0.212671f);
    const u64 M11 = pk2(0.715160f, 0.715160f);
    const u64 M12 = pk2(0.072169f, 0.072169f);
    const u64 M20 = pk2(0.019334f / 1.08883f, 0.019334f / 1.08883f);
    const u64 M21 = pk2(0.119193f / 1.08883f, 0.119193f / 1.08883f);
    const u64 M22 = pk2(0.950227f / 1.08883f, 0.950227f / 1.08883f);
    const u64 NEG1 = pk2(-1.0f, -1.0f);
    const u64 K5   = pk2(500.0f / 255.0f, 500.0f / 255.0f);
    const u64 K2_  = pk2(200.0f / 255.0f, 200.0f / 255.0f);
    const u64 K128 = pk2(128.0f / 255.0f, 128.0f / 255.0f);

    const int base4 = img * (NPIX * 3 / 4) + sub * (K2_PX * 3 / 4);
    const float4* in4 = (const float4*)x   + base4;
    float4*       o4  = (float4*)      out + base4;

    #pragma unroll
    for (int j = 0; j < K2_GROUPS; j++) {
        int gi = tid + j * THREADS;
        float4 v0 = in4[gi * 3 + 0];
        float4 v1 = in4[gi * 3 + 1];
        float4 v2 = in4[gi * 3 + 2];

        float Lp[4], Ap[4], Bp[4];

        // two pixel pairs: (0,1) and (2,3)
        #pragma unroll
        for (int h = 0; h < 2; h++) {
            float cr0 = (h == 0) ? v0.x : v1.z;
            float cr1 = (h == 0) ? v0.w : v2.y;
            float cg0 = (h == 0) ? v0.y : v1.w;
            float cg1 = (h == 0) ? v1.x : v2.z;
            float cb0 = (h == 0) ? v0.z : v2.x;
            float cb1 = (h == 0) ? v1.y : v2.w;

            // scalar gamma (MUFU boundary) -> pack pairs
            u64 r2 = pk2(srgb_lin(cr0), srgb_lin(cr1));
            u64 g2 = pk2(srgb_lin(cg0), srgb_lin(cg1));
            u64 b2 = pk2(srgb_lin(cb0), srgb_lin(cb1));

            // packed 3x3 matrix (mov-free chain)
            u64 X2 = fma2(r2, M00, fma2(g2, M01, mul2(b2, M02)));
            u64 Y2 = fma2(r2, M10, fma2(g2, M11, mul2(b2, M12)));
            u64 Z2 = fma2(r2, M20, fma2(g2, M21, mul2(b2, M22)));

            // scalar xyz_f (MUFU boundary)
            float X0, X1, Y0, Y1, Z0, Z1;
            upk2(X2, X0, X1);  upk2(Y2, Y0, Y1);  upk2(Z2, Z0, Z1);
            u64 fx2 = pk2(xyz_f(X0), xyz_f(X1));
            u64 fy2 = pk2(xyz_f(Y0), xyz_f(Y1));
            u64 fz2 = pk2(xyz_f(Z0), xyz_f(Z1));

            // packed finals
            u64 L2v = fma2(fy2, SF2, NSF2);
            u64 dxy = fma2(fy2, NEG1, fx2);            // fx - fy
            u64 A2v = fma2(dxy, K5, K128);
            u64 dyz = fma2(fz2, NEG1, fy2);            // fy - fz
            u64 B2v = fma2(dyz, K2_, K128);

            upk2(L2v, Lp[2 * h], Lp[2 * h + 1]);
            upk2(A2v, Ap[2 * h], Ap[2 * h + 1]);
            upk2(B2v, Bp[2 * h], Bp[2 * h + 1]);
        }

        __stcs(&o4[gi * 3 + 0], make_float4(Lp[0], Ap[0], Bp[0], Lp[1]));
        __stcs(&o4[gi * 3 + 1], make_float4(Ap[1], Bp[1], Lp[2], Ap[2]));
        __stcs(&o4[gi * 3 + 2], make_float4(Bp[2], Lp[3], Ap[3], Bp[3]));
    }
}

extern "C" void kernel_launch(void* const* d_in, const int* in_sizes, int n_in,
                              void* d_out, int out_size) {
    const float* x   = (const float*)d_in[0];
    float*       out = (float*)d_out;

    minmax_kernel <<<NIMG * K1_SUBS, THREADS>>>(x);
    convert_kernel<<<NIMG * K2_SUBS, THREADS>>>(x, out);
}

// round 15
// speedup vs baseline: 1.0261x; 1.0261x over previous
#include <cuda_runtime.h>
#include <float.h>

// Fused sRGB->CIELab + per-image L min-max normalization. Two-kernel.
// R15 = R14 (hybrid f32x2 packing) + batched global loads: all LDG.128 for a
// thread's groups issued before the math, deepening MLP to hide DRAM latency.
// K1: per-image Y min/max, 4 CTAs/image, loads batched 2-groups-ahead.
// K2: full Lab + normalize, 8 CTAs/image, both groups' loads hoisted,
//     reverse image order, streaming stores.

#define NPIX      16384
#define NIMG      512
#define K1_SUBS   4
#define K2_SUBS   8
#define THREADS   256
#define K1_PX     (NPIX / K1_SUBS)         // 4096
#define K2_PX     (NPIX / K2_SUBS)         // 2048
#define K1_GROUPS (K1_PX / (THREADS * 4))  // 4
#define K2_GROUPS (K2_PX / (THREADS * 4))  // 2

typedef unsigned long long u64;

__device__ float g_pmin[NIMG * K1_SUBS];
__device__ float g_pmax[NIMG * K1_SUBS];

// ---------------- f32x2 packed helpers ----------------
__device__ __forceinline__ u64 pk2(float lo, float hi) {
    u64 d; asm("mov.b64 %0, {%1, %2};" : "=l"(d) : "f"(lo), "f"(hi)); return d;
}
__device__ __forceinline__ void upk2(u64 d, float& lo, float& hi) {
    asm("mov.b64 {%0, %1}, %2;" : "=f"(lo), "=f"(hi) : "l"(d));
}
__device__ __forceinline__ u64 fma2(u64 a, u64 b, u64 c) {
    u64 d; asm("fma.rn.f32x2 %0, %1, %2, %3;" : "=l"(d) : "l"(a), "l"(b), "l"(c)); return d;
}
__device__ __forceinline__ u64 mul2(u64 a, u64 b) {
    u64 d; asm("mul.rn.f32x2 %0, %1, %2;" : "=l"(d) : "l"(a), "l"(b)); return d;
}

__device__ __forceinline__ float mufu_lg2(float x) {
    float r; asm("lg2.approx.f32 %0, %1;" : "=f"(r) : "f"(x)); return r;
}
__device__ __forceinline__ float mufu_ex2(float x) {
    float r; asm("ex2.approx.f32 %0, %1;" : "=f"(r) : "f"(x)); return r;
}
__device__ __forceinline__ float mufu_rcp(float x) {
    float r; asm("rcp.approx.f32 %0, %1;" : "=f"(r) : "f"(x)); return r;
}

__device__ __forceinline__ float srgb_lin(float c) {
    float t = fmaf(c, 1.0f / 1.055f, 0.055f / 1.055f);
    float p = mufu_ex2(2.4f * mufu_lg2(t));
    return (c > 0.04045f) ? p : c * (1.0f / 12.92f);
}

__device__ __forceinline__ float xyz_f(float t) {
    float cr = mufu_ex2((1.0f / 3.0f) * mufu_lg2(t));
    return (t > 0.008856f) ? cr : fmaf(t, 7.787f, 16.0f / 116.0f);
}

// ---------------------------------------------------------------- K1
__global__ void __launch_bounds__(THREADS)
minmax_kernel(const float* __restrict__ x) {
    __shared__ float red[16];
    const int bid = blockIdx.x;
    const int tid = threadIdx.x;

    const float4* in4 = (const float4*)x + bid * (K1_PX * 3 / 4);

    const u64 MY0 = pk2(0.212671f, 0.212671f);
    const u64 MY1 = pk2(0.715160f, 0.715160f);
    const u64 MY2 = pk2(0.072169f, 0.072169f);

    float ymin = FLT_MAX, ymax = -FLT_MAX;

    // two batches of 2 groups: 6 LDG.128 in flight before any math
    #pragma unroll
    for (int bb = 0; bb < K1_GROUPS / 2; bb++) {
        int g0 = tid + (2 * bb + 0) * THREADS;
        int g1 = tid + (2 * bb + 1) * THREADS;

        float4 a0 = in4[g0 * 3 + 0];
        float4 a1 = in4[g0 * 3 + 1];
        float4 a2 = in4[g0 * 3 + 2];
        float4 b0 = in4[g1 * 3 + 0];
        float4 b1 = in4[g1 * 3 + 1];
        float4 b2 = in4[g1 * 3 + 2];

        #pragma unroll
        for (int k = 0; k < 2; k++) {
            float4 v0 = k ? b0 : a0;
            float4 v1 = k ? b1 : a1;
            float4 v2 = k ? b2 : a2;

            u64 rA = pk2(srgb_lin(v0.x), srgb_lin(v0.w));
            u64 gA = pk2(srgb_lin(v0.y), srgb_lin(v1.x));
            u64 bA = pk2(srgb_lin(v0.z), srgb_lin(v1.y));
            u64 rB = pk2(srgb_lin(v1.z), srgb_lin(v2.y));
            u64 gB = pk2(srgb_lin(v1.w), srgb_lin(v2.z));
            u64 bB = pk2(srgb_lin(v2.x), srgb_lin(v2.w));

            u64 yA = fma2(rA, MY0, fma2(gA, MY1, mul2(bA, MY2)));
            u64 yB = fma2(rB, MY0, fma2(gB, MY1, mul2(bB, MY2)));

            float y0, y1, y2, y3;
            upk2(yA, y0, y1);  upk2(yB, y2, y3);
            ymin = fminf(fminf(fminf(ymin, y0), fminf(y1, y2)), y3);
            ymax = fmaxf(fmaxf(fmaxf(ymax, y0), fmaxf(y1, y2)), y3);
        }
    }

    #pragma unroll
    for (int off = 16; off > 0; off >>= 1) {
        ymin = fminf(ymin, __shfl_xor_sync(0xffffffffu, ymin, off));
        ymax = fmaxf(ymax, __shfl_xor_sync(0xffffffffu, ymax, off));
    }
    int lane = tid & 31, wid = tid >> 5;
    if (lane == 0) { red[wid] = ymin; red[8 + wid] = ymax; }
    __syncthreads();
    if (tid == 0) {
        float mn = red[0], mx = red[8];
        #pragma unroll
        for (int i = 1; i < 8; i++) {
            mn = fminf(mn, red[i]);
            mx = fmaxf(mx, red[8 + i]);
        }
        g_pmin[bid] = mn;
        g_pmax[bid] = mx;
    }
}

// ---------------------------------------------------------------- K2
__global__ void __launch_bounds__(THREADS)
convert_kernel(const float* __restrict__ x, float* __restrict__ out) {
    const int bid = blockIdx.x;
    const int img = (NIMG - 1) - (bid >> 3);   // reverse order for L2 reuse
    const int sub = bid & 7;
    const int tid = threadIdx.x;

    float ymn = fminf(fminf(g_pmin[img * 4 + 0], g_pmin[img * 4 + 1]),
                      fminf(g_pmin[img * 4 + 2], g_pmin[img * 4 + 3]));
    float ymx = fmaxf(fmaxf(g_pmax[img * 4 + 0], g_pmax[img * 4 + 1]),
                      fmaxf(g_pmax[img * 4 + 2], g_pmax[img * 4 + 3]));
    float fmin = xyz_f(ymn);
    float sf   = mufu_rcp(xyz_f(ymx) - fmin);
    const u64 SF2  = pk2(sf, sf);
    const u64 NSF2 = pk2(-fmin * sf, -fmin * sf);

    const u64 M00 = pk2(0.412453f / 0.95047f, 0.412453f / 0.95047f);
    const u64 M01 = pk2(0.357580f / 0.95047f, 0.357580f / 0.95047f);
    const u64 M02 = pk2(0.180423f / 0.95047f, 0.180423f / 0.95047f);
    const u64 M10 = pk2(0.212671f, 0.212671f);
    const u64 M11 = pk2(0.715160f, 0.715160f);
    const u64 M12 = pk2(0.072169f, 0.072169f);
    const u64 M20 = pk2(0.019334f / 1.08883f, 0.019334f / 1.08883f);
    const u64 M21 = pk2(0.119193f / 1.08883f, 0.119193f / 1.08883f);
    const u64 M22 = pk2(0.950227f / 1.08883f, 0.950227f / 1.08883f);
    const u64 NEG1 = pk2(-1.0f, -1.0f);
    const u64 K5   = pk2(500.0f / 255.0f, 500.0f / 255.0f);
    const u64 K2_  = pk2(200.0f / 255.0f, 200.0f / 255.0f);
    const u64 K128 = pk2(128.0f / 255.0f, 128.0f / 255.0f);

    const int base4 = img * (NPIX * 3 / 4) + sub * (K2_PX * 3 / 4);
    const float4* in4 = (const float4*)x   + base4;
    float4*       o4  = (float4*)      out + base4;

    // ---- hoist ALL loads: 6 LDG.128 in flight before any math ----
    const int gi0 = tid;
    const int gi1 = tid + THREADS;
    float4 w0 = in4[gi0 * 3 + 0];
    float4 w1 = in4[gi0 * 3 + 1];
    float4 w2 = in4[gi0 * 3 + 2];
    float4 w3 = in4[gi1 * 3 + 0];
    float4 w4 = in4[gi1 * 3 + 1];
    float4 w5 = in4[gi1 * 3 + 2];

    #pragma unroll
    for (int j = 0; j < K2_GROUPS; j++) {
        int gi = j ? gi1 : gi0;
        float4 v0 = j ? w3 : w0;
        float4 v1 = j ? w4 : w1;
        float4 v2 = j ? w5 : w2;

        float Lp[4], Ap[4], Bp[4];

        #pragma unroll
        for (int h = 0; h < 2; h++) {
            float cr0 = (h == 0) ? v0.x : v1.z;
            float cr1 = (h == 0) ? v0.w : v2.y;
            float cg0 = (h == 0) ? v0.y : v1.w;
            float cg1 = (h == 0) ? v1.x : v2.z;
            float cb0 = (h == 0) ? v0.z : v2.x;
            float cb1 = (h == 0) ? v1.y : v2.w;

            u64 r2 = pk2(srgb_lin(cr0), srgb_lin(cr1));
            u64 g2 = pk2(srgb_lin(cg0), srgb_lin(cg1));
            u64 b2 = pk2(srgb_lin(cb0), srgb_lin(cb1));

            u64 X2 = fma2(r2, M00, fma2(g2, M01, mul2(b2, M02)));
            u64 Y2 = fma2(r2, M10, fma2(g2, M11, mul2(b2, M12)));
            u64 Z2 = fma2(r2, M20, fma2(g2, M21, mul2(b2, M22)));

            float X0, X1, Y0, Y1, Z0, Z1;
            upk2(X2, X0, X1);  upk2(Y2, Y0, Y1);  upk2(Z2, Z0, Z1);
            u64 fx2 = pk2(xyz_f(X0), xyz_f(X1));
            u64 fy2 = pk2(xyz_f(Y0), xyz_f(Y1));
            u64 fz2 = pk2(xyz_f(Z0), xyz_f(Z1));

            u64 L2v = fma2(fy2, SF2, NSF2);
            u64 dxy = fma2(fy2, NEG1, fx2);
            u64 A2v = fma2(dxy, K5, K128);
            u64 dyz = fma2(fz2, NEG1, fy2);
            u64 B2v = fma2(dyz, K2_, K128);

            upk2(L2v, Lp[2 * h], Lp[2 * h + 1]);
            upk2(A2v, Ap[2 * h], Ap[2 * h + 1]);
            upk2(B2v, Bp[2 * h], Bp[2 * h + 1]);
        }

        __stcs(&o4[gi * 3 + 0], make_float4(Lp[0], Ap[0], Bp[0], Lp[1]));
        __stcs(&o4[gi * 3 + 1], make_float4(Ap[1], Bp[1], Lp[2], Ap[2]));
        __stcs(&o4[gi * 3 + 2], make_float4(Bp[2], Lp[3], Ap[3], Bp[3]));
    }
}

extern "C" void kernel_launch(void* const* d_in, const int* in_sizes, int n_in,
                              void* d_out, int out_size) {
    const float* x   = (const float*)d_in[0];
    float*       out = (float*)d_out;

    minmax_kernel <<<NIMG * K1_SUBS, THREADS>>>(x);
    convert_kernel<<<NIMG * K2_SUBS, THREADS>>>(x, out);
}